// round 13
// baseline (speedup 1.0000x reference)
#include <cuda_runtime.h>

#define VOCAB 500
#define EMB   64
#define HID   64
#define BATCH 512
#define SEQ   512

// Precomputed input projection: E'[v][i] = b_ih0[i] + sum_j emb[v][j]*W_ih0[i][j]
__device__ float g_xproj[VOCAB * HID];

typedef unsigned long long u64;

__device__ __forceinline__ void fma2(u64 &d, u64 a, u64 b) {
    asm("fma.rn.f32x2 %0, %1, %2, %0;" : "+l"(d) : "l"(a), "l"(b));
}
__device__ __forceinline__ u64 add2(u64 a, u64 b) {
    u64 r; asm("add.rn.f32x2 %0, %1, %2;" : "=l"(r) : "l"(a), "l"(b)); return r;
}
__device__ __forceinline__ float hsum2(u64 a, u64 b) {
    u64 s = add2(a, b);
    float lo, hi;
    asm("mov.b64 {%0,%1}, %2;" : "=f"(lo), "=f"(hi) : "l"(s));
    return lo + hi;
}
// HW tanh: MUFU.TANH, ~16 cyc, rel err ~2^-11
__device__ __forceinline__ float fast_tanh(float x) {
    float r;
    asm("tanh.approx.f32 %0, %1;" : "=f"(r) : "f"(x));
    return r;
}

// ---------------------------------------------------------------------------
// Kernel 1: fold embedding + layer-0 input projection into a 500x64 LUT.
// ---------------------------------------------------------------------------
__global__ void xproj_kernel(const float* __restrict__ emb,
                             const float* __restrict__ W_ih0,
                             const float* __restrict__ b_ih0) {
    __shared__ float se[EMB];
    const int v = blockIdx.x;
    const int i = threadIdx.x;
    se[i] = emb[v * EMB + i];
    __syncthreads();
    float acc = 0.0f;
    const float4* wr = (const float4*)(W_ih0 + i * EMB);
    #pragma unroll
    for (int q = 0; q < 16; q++) {
        float4 wv = __ldg(wr + q);
        acc += wv.x * se[4*q+0] + wv.y * se[4*q+1] + wv.z * se[4*q+2] + wv.w * se[4*q+3];
    }
    g_xproj[v * HID + i] = acc + b_ih0[i];
}

// ---------------------------------------------------------------------------
// Kernel 2: sequential scan. CTA = 64 threads = ONE batch row; grid = 512.
// ~252 regs -> 4 CTAs/SM by regfile; the critical SMs carry 4 rows in FOUR
// independent __syncthreads domains (vs R12's two), with 2-warp barriers
// (floor ~7 cyc, minimal straggler scope). One CTA's fma stream fills the
// others' barrier/LDS/MUFU latency.
// Per step: ONE barrier, ONE merged 96-fma2 region (s = Wih1.h1_t,
// q = Whh0.h1_t, r = Whh1.h2_{t-1}; 6 round-robin accumulators).
// h1 is SOFTWARE-PIPELINED across the barrier: as soon as cq = Whh0.h1_t is
// reduced, h1_{t+1} = tanh(cq + x_{t+1} + b1) is computed and stored in the
// region tail (targets parity buffer cur^1; its previous readers finished
// before bar_t, so the write is race-free). The top of each iteration only
// publishes h2_{t-1}, so bar->tanh leaves the serial path.
// Parity buffers: iter t reads sh1[cur], sh2[cur] (cur = t&1); h1_{t+1} is
// stored to sh1[cur^1] at the tail of iter t; h2_{t-1} to sh2[cur] at the
// top. Iter 0 reads the zeros it wrote (h_{-1} = 0, h1_0 staged pre-loop).
// Index dtype (int64/int32) detected from the global first 128 words.
// ---------------------------------------------------------------------------
__global__ void __launch_bounds__(64, 4)
scan_kernel(const int* __restrict__ xw,
            const float* __restrict__ W_hh0,
            const float* __restrict__ b_hh0,
            const float* __restrict__ W_ih1,
            const float* __restrict__ W_hh1,
            const float* __restrict__ b_ih1,
            const float* __restrict__ b_hh1,
            const float* __restrict__ fc_w,
            const float* __restrict__ fc_b,
            float* __restrict__ out) {
    __shared__ __align__(16) float sh1[2][HID];
    __shared__ __align__(16) float sh2[2][HID];
    __shared__ int   sidx[SEQ];
    __shared__ float swsum[2];
    __shared__ int   s_is64;

    const int i    = threadIdx.x;       // owned output, 0..63
    const int lane = i & 31;
    const int half = i >> 5;            // warp within CTA
    const int b    = blockIdx.x;        // batch row

    // --- weights: full row i of each matrix, as f32x2 pairs (192 regs) ---
    u64 w0[32], w1[32], w2[32];         // W_hh0, W_ih1, W_hh1
    {
        const u64* q0 = (const u64*)(W_hh0 + i * HID);
        const u64* q1 = (const u64*)(W_ih1 + i * HID);
        const u64* q2 = (const u64*)(W_hh1 + i * HID);
        #pragma unroll
        for (int q = 0; q < 32; q++) {
            w0[q] = __ldg(q0 + q);
            w1[q] = __ldg(q1 + q);
            w2[q] = __ldg(q2 + q);
        }
    }
    const float b1 = b_hh0[i];
    const float b2 = b_ih1[i] + b_hh1[i];

    // --- dtype probe on GLOBAL first 128 words (valid for either layout) ---
    if (i == 0) {
        int z = 0;
        #pragma unroll
        for (int k = 1; k < 128; k += 2) z |= xw[k];
        s_is64 = (z == 0);
    }
    __syncthreads();
    {
        const int is64 = s_is64;
        const int base = b * SEQ;
        #pragma unroll
        for (int k = i; k < SEQ; k += 64) {
            int v = is64 ? xw[2 * (base + k)] : xw[base + k];
            sidx[k] = min(max(v, 0), VOCAB - 1);
        }
    }

    // prologue: h1_0 = tanh(x_0 + b1) staged into parity buffer 0;
    // h2_{-1} = 0 published at the top of iter 0.
    const float x0 = __ldg(&g_xproj[sidx[0] * HID + i]);
    __syncthreads();                    // sidx visible
    sh1[0][i] = fast_tanh(x0 + b1);

    float h2n = 0.0f;                   // h2_{t-1}
    float xn  = __ldg(&g_xproj[sidx[1] * HID + i]);   // x_1 (for h1_1)

    #pragma unroll 1
    for (int t = 0; t < SEQ; t++) {
        const int cur = t & 1;

        sh2[cur][i] = h2n;              // publish h2_{t-1}
        __syncthreads();                // the ONLY barrier in the step

        const int tn = (t + 2 < SEQ) ? (t + 2) : (SEQ - 1);
        const float xc = xn;            // x_{t+1}
        xn = __ldg(&g_xproj[sidx[tn] * HID + i]);     // prefetch x_{t+2}

        // merged region over buffers [cur]:
        //   s = Wih1.h1_t, q = Whh0.h1_t, r = Whh1.h2_{t-1}
        const ulonglong2* H1 = (const ulonglong2*)sh1[cur];
        const ulonglong2* H2 = (const ulonglong2*)sh2[cur];
        u64 s0 = 0, s1 = 0, q0 = 0, q1v = 0, r0 = 0, r1 = 0;
        #pragma unroll
        for (int m = 0; m < 16; m++) {
            ulonglong2 ha = H1[m];
            fma2(q0,  w0[2*m],   ha.x);
            fma2(q1v, w0[2*m+1], ha.y);
            fma2(s0,  w1[2*m],   ha.x);
            fma2(s1,  w1[2*m+1], ha.y);
            ulonglong2 ga = H2[m];
            fma2(r0,  w2[2*m],   ga.x);
            fma2(r1,  w2[2*m+1], ga.y);
        }
        // h1_{t+1} pipelined across the barrier: store into buffer cur^1
        // (its previous readers were ordered before bar_t).
        const float cq = hsum2(q0, q1v);
        sh1[cur ^ 1][i] = fast_tanh(cq + xc + b1);

        // h2_t = tanh(Wih1.h1_t + Whh1.h2_{t-1} + b2) — published next iter
        h2n = fast_tanh(hsum2(s0, s1) + hsum2(r0, r1) + b2);
    }

    // --- final projection: out[b] = fc_w . h2 + fc_b ---
    float val = __ldg(&fc_w[i]) * h2n;
    #pragma unroll
    for (int off = 16; off; off >>= 1)
        val += __shfl_xor_sync(0xffffffffu, val, off);
    if (lane == 0) swsum[half] = val;
    __syncthreads();
    if (i == 0) out[b] = swsum[0] + swsum[1] + fc_b[0];
}

// ---------------------------------------------------------------------------
extern "C" void kernel_launch(void* const* d_in, const int* in_sizes, int n_in,
                              void* d_out, int out_size) {
    const int*   x_raw = (const int*)d_in[0];
    const float* emb   = (const float*)d_in[1];
    const float* W_ih0 = (const float*)d_in[2];
    const float* W_hh0 = (const float*)d_in[3];
    const float* b_ih0 = (const float*)d_in[4];
    const float* b_hh0 = (const float*)d_in[5];
    const float* W_ih1 = (const float*)d_in[6];
    const float* W_hh1 = (const float*)d_in[7];
    const float* b_ih1 = (const float*)d_in[8];
    const float* b_hh1 = (const float*)d_in[9];
    const float* fc_w  = (const float*)d_in[10];
    const float* fc_b  = (const float*)d_in[11];
    float*       out   = (float*)d_out;

    xproj_kernel<<<VOCAB, HID>>>(emb, W_ih0, b_ih0);
    scan_kernel<<<BATCH, 64>>>(
        x_raw, W_hh0, b_hh0, W_ih1, W_hh1, b_ih1, b_hh1, fc_w, fc_b, out);
}

// round 14
// speedup vs baseline: 1.0485x; 1.0485x over previous
#include <cuda_runtime.h>

#define VOCAB 500
#define EMB   64
#define HID   64
#define BATCH 512
#define SEQ   512

// Precomputed input projection: E'[v][i] = b_ih0[i] + sum_j emb[v][j]*W_ih0[i][j]
__device__ float g_xproj[VOCAB * HID];

typedef unsigned long long u64;

__device__ __forceinline__ void fma2(u64 &d, u64 a, u64 b) {
    asm("fma.rn.f32x2 %0, %1, %2, %0;" : "+l"(d) : "l"(a), "l"(b));
}
__device__ __forceinline__ u64 add2(u64 a, u64 b) {
    u64 r; asm("add.rn.f32x2 %0, %1, %2;" : "=l"(r) : "l"(a), "l"(b)); return r;
}
__device__ __forceinline__ float hsum1(u64 a) {
    float lo, hi;
    asm("mov.b64 {%0,%1}, %2;" : "=f"(lo), "=f"(hi) : "l"(a));
    return lo + hi;
}
// HW tanh: MUFU.TANH, ~16 cyc, rel err ~2^-11
__device__ __forceinline__ float fast_tanh(float x) {
    float r;
    asm("tanh.approx.f32 %0, %1;" : "=f"(r) : "f"(x));
    return r;
}

// ---------------------------------------------------------------------------
// Kernel 1: fold embedding + layer-0 input projection into a 500x64 LUT.
// ---------------------------------------------------------------------------
__global__ void xproj_kernel(const float* __restrict__ emb,
                             const float* __restrict__ W_ih0,
                             const float* __restrict__ b_ih0) {
    __shared__ float se[EMB];
    const int v = blockIdx.x;
    const int i = threadIdx.x;
    se[i] = emb[v * EMB + i];
    __syncthreads();
    float acc = 0.0f;
    const float4* wr = (const float4*)(W_ih0 + i * EMB);
    #pragma unroll
    for (int q = 0; q < 16; q++) {
        float4 wv = __ldg(wr + q);
        acc += wv.x * se[4*q+0] + wv.y * se[4*q+1] + wv.z * se[4*q+2] + wv.w * se[4*q+3];
    }
    g_xproj[v * HID + i] = acc + b_ih0[i];
}

// ---------------------------------------------------------------------------
// Kernel 2: sequential scan with HALF-J OWNERSHIP.
// CTA = 64 threads = 1 batch row; grid = 512; ~4 CTAs/SM.
// Warp w owns j-half [32w, 32w+32) AND finishes h for i in that same range:
//   - matvec: thread (w,L) computes partial dots for rows i0=L, i1=L+32
//     over its j-half (weights: 2 rows x 3 mats x 32 cols = 96 u64 regs);
//     each warp loads only ITS h-half -> 16 broadcast LDS.128/warp/step
//     (halved vs full-j designs, which ran L1 at 62%).
//   - exchange: (q, u=s+r) partials per i via smem (parity-buffered spart),
//     ONE __syncthreads per step.
//   - finish: warp w computes tanh for i = 32w+L and republishes h1/h2 into
//     its own j-half of the single h buffers. Since matvec j-range ==
//     finish i-range, ALL h traffic is intra-warp: a __syncwarp (~23 cyc)
//     is the only ordering needed — no second barrier, no h double-buffer.
// spart parity: write(t)->slot t&1; partner reads after bar(t), before its
// bar(t+1) arrival; next write to that slot is after bar(t+1). Race-free.
// Index dtype (int64/int32) detected from the global first 128 words.
// ---------------------------------------------------------------------------
__global__ void __launch_bounds__(64, 4)
scan_kernel(const int* __restrict__ xw,
            const float* __restrict__ W_hh0,
            const float* __restrict__ b_hh0,
            const float* __restrict__ W_ih1,
            const float* __restrict__ W_hh1,
            const float* __restrict__ b_ih1,
            const float* __restrict__ b_hh1,
            const float* __restrict__ fc_w,
            const float* __restrict__ fc_b,
            float* __restrict__ out) {
    __shared__ __align__(16) float sh1[HID];       // single-buffered h1
    __shared__ __align__(16) float sh2[HID];       // single-buffered h2
    __shared__ float2 spart[2][2][HID];            // [parity][jhalf][i] = (q, u)
    __shared__ int    sidx[SEQ];
    __shared__ float  swsum[2];
    __shared__ int    s_is64;

    const int tid  = threadIdx.x;
    const int w    = tid >> 5;           // j-half / finish-half
    const int L    = tid & 31;
    const int i0   = L;                  // compute rows (weights)
    const int i1   = L + 32;
    const int ifin = w * 32 + L;         // finished output row
    const int jbase = w * 32;
    const int b    = blockIdx.x;

    // --- weights: rows i0,i1 x own j-half, f32x2 pairs (96 u64 = 192 regs) ---
    u64 w00[16], w01[16], w10[16], w11[16], w20[16], w21[16];
    {
        const u64* p00 = (const u64*)(W_hh0 + i0 * HID + jbase);
        const u64* p01 = (const u64*)(W_hh0 + i1 * HID + jbase);
        const u64* p10 = (const u64*)(W_ih1 + i0 * HID + jbase);
        const u64* p11 = (const u64*)(W_ih1 + i1 * HID + jbase);
        const u64* p20 = (const u64*)(W_hh1 + i0 * HID + jbase);
        const u64* p21 = (const u64*)(W_hh1 + i1 * HID + jbase);
        #pragma unroll
        for (int q = 0; q < 16; q++) {
            w00[q] = __ldg(p00 + q);  w01[q] = __ldg(p01 + q);
            w10[q] = __ldg(p10 + q);  w11[q] = __ldg(p11 + q);
            w20[q] = __ldg(p20 + q);  w21[q] = __ldg(p21 + q);
        }
    }
    const float b1f = b_hh0[ifin];
    const float b2f = b_ih1[ifin] + b_hh1[ifin];

    // --- dtype probe on GLOBAL first 128 words (valid for either layout) ---
    if (tid == 0) {
        int z = 0;
        #pragma unroll
        for (int k = 1; k < 128; k += 2) z |= xw[k];
        s_is64 = (z == 0);
    }
    __syncthreads();
    {
        const int is64 = s_is64;
        const int base = b * SEQ;
        #pragma unroll
        for (int k = tid; k < SEQ; k += 64) {
            int v = is64 ? xw[2 * (base + k)] : xw[base + k];
            sidx[k] = min(max(v, 0), VOCAB - 1);
        }
    }
    __syncthreads();                      // sidx visible to both warps

    // prologue: h1_0 = tanh(x_0 + b1), h2_{-1} = 0, published into OWN half
    sh1[ifin] = fast_tanh(__ldg(&g_xproj[sidx[0] * HID + ifin]) + b1f);
    sh2[ifin] = 0.0f;
    __syncwarp();                         // intra-warp h visibility

    const ulonglong2* H1 = (const ulonglong2*)(sh1 + jbase);
    const ulonglong2* H2 = (const ulonglong2*)(sh2 + jbase);

    float xn  = __ldg(&g_xproj[sidx[1] * HID + ifin]);   // x_1
    float h2n = 0.0f;

    #pragma unroll 1
    for (int t = 0; t < SEQ; t++) {
        const int p = t & 1;

        // matvec over own j-half of (h1_t, h2_{t-1}): 6 dots, 96 fma2
        u64 qa = 0, qb = 0, sa = 0, sb = 0, ra = 0, rb = 0;
        #pragma unroll
        for (int m = 0; m < 8; m++) {
            ulonglong2 h = H1[m];
            fma2(qa, w00[2*m], h.x);  fma2(qa, w00[2*m+1], h.y);
            fma2(qb, w01[2*m], h.x);  fma2(qb, w01[2*m+1], h.y);
            fma2(sa, w10[2*m], h.x);  fma2(sa, w10[2*m+1], h.y);
            fma2(sb, w11[2*m], h.x);  fma2(sb, w11[2*m+1], h.y);
            ulonglong2 g = H2[m];
            fma2(ra, w20[2*m], g.x);  fma2(ra, w20[2*m+1], g.y);
            fma2(rb, w21[2*m], g.x);  fma2(rb, w21[2*m+1], g.y);
        }
        // partials: q = Whh0.h1 half-sum; u = (Wih1.h1 + Whh1.h2) half-sum
        spart[p][w][i0] = make_float2(hsum1(qa), hsum1(add2(sa, ra)));
        spart[p][w][i1] = make_float2(hsum1(qb), hsum1(add2(sb, rb)));
        __syncthreads();                  // the ONLY CTA barrier in the step

        const int tn = (t + 2 < SEQ) ? (t + 2) : (SEQ - 1);
        const float xc = xn;              // x_{t+1}
        xn = __ldg(&g_xproj[sidx[tn] * HID + ifin]);     // prefetch x_{t+2}

        // finish own i: combine both j-halves, apply tanh, republish h
        const float2 e0 = spart[p][0][ifin];
        const float2 e1 = spart[p][1][ifin];
        const float h1n = fast_tanh(e0.x + e1.x + xc + b1f);  // h1_{t+1}
        h2n             = fast_tanh(e0.y + e1.y + b2f);       // h2_t
        sh1[ifin] = h1n;
        sh2[ifin] = h2n;
        __syncwarp();                     // intra-warp republish ordering
    }

    // --- final projection: out[b] = fc_w . h2 + fc_b ---
    float val = __ldg(&fc_w[ifin]) * h2n;
    #pragma unroll
    for (int off = 16; off; off >>= 1)
        val += __shfl_xor_sync(0xffffffffu, val, off);
    if (L == 0) swsum[w] = val;
    __syncthreads();
    if (tid == 0) out[b] = swsum[0] + swsum[1] + fc_b[0];
}

// ---------------------------------------------------------------------------
extern "C" void kernel_launch(void* const* d_in, const int* in_sizes, int n_in,
                              void* d_out, int out_size) {
    const int*   x_raw = (const int*)d_in[0];
    const float* emb   = (const float*)d_in[1];
    const float* W_ih0 = (const float*)d_in[2];
    const float* W_hh0 = (const float*)d_in[3];
    const float* b_ih0 = (const float*)d_in[4];
    const float* b_hh0 = (const float*)d_in[5];
    const float* W_ih1 = (const float*)d_in[6];
    const float* W_hh1 = (const float*)d_in[7];
    const float* b_ih1 = (const float*)d_in[8];
    const float* b_hh1 = (const float*)d_in[9];
    const float* fc_w  = (const float*)d_in[10];
    const float* fc_b  = (const float*)d_in[11];
    float*       out   = (float*)d_out;

    xproj_kernel<<<VOCAB, HID>>>(emb, W_ih0, b_ih0);
    scan_kernel<<<BATCH, 64>>>(
        x_raw, W_hh0, b_hh0, W_ih1, W_hh1, b_ih1, b_hh1, fc_w, fc_b, out);
}